// round 12
// baseline (speedup 1.0000x reference)
#include <cuda_runtime.h>
#include <cuda_fp16.h>
#include <cstdint>

#define B_   8
#define C_   256
#define HW_  16384
#define NG_  524288.0f
#define LDX1 72        // Xs pad for 64-px tiles (k_m)
#define LDX2 136       // Xs pad for 128-px tiles (68 words, mod 32 = 4 -> conflict-free)
#define LDWS 40        // W chunk row pad (halves)
#define SZW  (256 * LDWS)

// scratch (device globals; allocation APIs forbidden)
__device__ __half g_q[(size_t)B_ * C_ * HW_];
__device__ __half g_k[(size_t)B_ * C_ * HW_];
__device__ __half g_v[(size_t)B_ * C_ * HW_];
__device__ float  g_kvn[B_ * C_ * C_];
__device__ __half g_M[B_ * C_ * C_];
__device__ float  g_ksum[B_ * C_];
__device__ float  g_sum[B_ * 8];
__device__ float  g_sq[B_ * 8];
__device__ __half g_Wh[4 * 65536];   // fp16 Wq,Wk,Wv,Wp row-major [o][c]

__device__ __forceinline__ float elu1(float x) { return x > 0.f ? x + 1.f : __expf(x); }
__device__ __forceinline__ uint32_t s2u(const void* p) { return (uint32_t)__cvta_generic_to_shared(p); }
__device__ __forceinline__ void mma16(float c[4], const uint32_t a[4], const uint32_t b0, const uint32_t b1) {
    asm volatile("mma.sync.aligned.m16n8k16.row.col.f32.f16.f16.f32 "
        "{%0,%1,%2,%3},{%4,%5,%6,%7},{%8,%9},{%0,%1,%2,%3};\n"
        : "+f"(c[0]), "+f"(c[1]), "+f"(c[2]), "+f"(c[3])
        : "r"(a[0]), "r"(a[1]), "r"(a[2]), "r"(a[3]), "r"(b0), "r"(b1));
}
__device__ __forceinline__ void ldsm4(uint32_t r[4], uint32_t addr) {
    asm volatile("ldmatrix.sync.aligned.m8n8.x4.shared.b16 {%0,%1,%2,%3}, [%4];"
        : "=r"(r[0]), "=r"(r[1]), "=r"(r[2]), "=r"(r[3]) : "r"(addr));
}
__device__ __forceinline__ void ldsm4t(uint32_t r[4], uint32_t addr) {
    asm volatile("ldmatrix.sync.aligned.m8n8.x4.trans.shared.b16 {%0,%1,%2,%3}, [%4];"
        : "=r"(r[0]), "=r"(r[1]), "=r"(r[2]), "=r"(r[3]) : "r"(addr));
}
__device__ __forceinline__ void cp16(__half* dst, const __half* src) {
    asm volatile("cp.async.ca.shared.global [%0], [%1], 16;\n" :: "r"(s2u(dst)), "l"(src));
}
__device__ __forceinline__ void red2(float* addr, float a, float b) {
    asm volatile("red.global.add.v2.f32 [%0], {%1, %2};" :: "l"(addr), "f"(a), "f"(b) : "memory");
}
#define CP_COMMIT() asm volatile("cp.async.commit_group;\n")
#define CP_WAIT0()  asm volatile("cp.async.wait_group 0;\n")

// stage a 256-row x 32-half W chunk (gmem row stride 256 halves); NT = threads
template <int NT>
__device__ __forceinline__ void stageW(__half* buf, const __half* src, int tid) {
#pragma unroll
    for (int i = 0; i < 1024 / NT; i++) {
        int lin = i * NT + tid, r = lin >> 2, s = lin & 3;
        cp16(buf + r * LDWS + s * 8, src + (size_t)r * 256 + s * 8);
    }
}

// gemm body: chunk 0 pre-staged+committed by caller. Double buffer, ONE sync/chunk,
// stage AFTER sync (race-free). LDX = Xs row stride; NT = block threads.
template <int LDX, int NT>
__device__ __forceinline__ void gemm_body(const __half* __restrict__ Wg, uint32_t xs,
                                          __half* Wbuf, int tid, int lane, int wo, int wp,
                                          float acc[4][4][4]) {
#pragma unroll
    for (int m = 0; m < 4; m++)
#pragma unroll
        for (int n = 0; n < 4; n++)
#pragma unroll
            for (int i = 0; i < 4; i++) acc[m][n][i] = 0.f;
    uint32_t wbu = s2u(Wbuf);
    int rowA = lane & 15, colA = (lane & 16) >> 1;
    int rowB = (lane & 7) + (lane & 8), colB = (lane & 16) >> 1;
#pragma unroll 1
    for (int kc = 0; kc < 8; kc++) {
        CP_WAIT0();
        __syncthreads();
        if (kc < 7) { stageW<NT>(Wbuf + ((kc + 1) & 1) * SZW, Wg + (kc + 1) * 32, tid); CP_COMMIT(); }
        uint32_t wcb = wbu + ((kc & 1) * SZW) * 2;
#pragma unroll
        for (int ks = 0; ks < 2; ks++) {
            uint32_t A[4][4];
#pragma unroll
            for (int m = 0; m < 4; m++)
                ldsm4(A[m], wcb + ((wo * 64 + m * 16 + rowA) * LDWS + ks * 16 + colA) * 2);
            uint32_t Bv[2][4];
            int kg = kc * 32 + ks * 16;
#pragma unroll
            for (int t = 0; t < 2; t++)
                ldsm4t(Bv[t], xs + ((kg + rowB) * LDX + wp * 32 + t * 16 + colB) * 2);
#pragma unroll
            for (int m = 0; m < 4; m++)
#pragma unroll
                for (int n = 0; n < 4; n++)
                    mma16(acc[m][n], A[m], Bv[n >> 1][(n & 1) * 2], Bv[n >> 1][(n & 1) * 2 + 1]);
        }
    }
}

// ---------------- small kernels ----------------
__global__ void k0_zero() {
    int gid = blockIdx.x * 256 + threadIdx.x;
    *(float4*)(g_kvn + (size_t)gid * 4) = make_float4(0.f, 0.f, 0.f, 0.f);
    if (gid < B_ * C_) g_ksum[gid] = 0.f;
    if (gid < 64) { g_sum[gid] = 0.f; g_sq[gid] = 0.f; }
}
__global__ void k_prep(const float* __restrict__ Wq, const float* __restrict__ Wk,
                       const float* __restrict__ Wv, const float* __restrict__ Wp) {
    int i = blockIdx.x * 256 + threadIdx.x;
    g_Wh[i] = __float2half_rn(Wq[i]);
    g_Wh[65536 + i] = __float2half_rn(Wk[i]);
    g_Wh[131072 + i] = __float2half_rn(Wv[i]);
    g_Wh[196608 + i] = __float2half_rn(Wp[i]);
}
__global__ void __launch_bounds__(256) k_stats(const float* __restrict__ x) {
    int bg = blockIdx.y;
    const float* base = x + (size_t)bg * 524288 + blockIdx.x * 32768;
    int tid = threadIdx.x, lane = tid & 31, warp = tid >> 5;
    float s = 0.f, sq = 0.f;
    for (int i = tid; i < 8192; i += 256) {
        float4 v = *(const float4*)(base + i * 4);
        s += v.x + v.y + v.z + v.w;
        sq = fmaf(v.x, v.x, sq); sq = fmaf(v.y, v.y, sq);
        sq = fmaf(v.z, v.z, sq); sq = fmaf(v.w, v.w, sq);
    }
#pragma unroll
    for (int o = 16; o > 0; o >>= 1) {
        s += __shfl_xor_sync(~0u, s, o); sq += __shfl_xor_sync(~0u, sq, o);
    }
    __shared__ float rs[8], rq[8];
    if (lane == 0) { rs[warp] = s; rq[warp] = sq; }
    __syncthreads();
    if (tid == 0) {
        float S = 0.f, Q = 0.f;
#pragma unroll
        for (int i = 0; i < 8; i++) { S += rs[i]; Q += rq[i]; }
        atomicAdd(&g_sum[bg], S); atomicAdd(&g_sq[bg], Q);
    }
}

// ---------------- k_qkv: 512 threads, 256x128 tiles ----------------
__global__ void __launch_bounds__(512, 1) k_qkv(
    const float* __restrict__ x, const float* __restrict__ gamma, const float* __restrict__ beta,
    const float* __restrict__ bq, const float* __restrict__ bk, const float* __restrict__ bv) {
    extern __shared__ __half smh[];
    __half* Xs = smh;                          // [256 k][LDX2]
    __half* Wbuf = smh + 256 * LDX2;           // 2 x SZW
    float* sc = (float*)(smh + 256 * LDX2 + 2 * SZW);
    float* tb = sc + 256;
    int b = blockIdx.y, p0 = blockIdx.x * 128;
    int tid = threadIdx.x, lane = tid & 31, warp = tid >> 5;
    int wo = warp & 3, wp = warp >> 2, c2 = lane & 3;
    uint32_t xs = s2u(Xs);
    stageW<512>(Wbuf, g_Wh, tid); CP_COMMIT();
    if (tid < 256) {
        int c = tid, g = c >> 5;
        float mean = g_sum[b * 8 + g] * (1.0f / NG_);
        float var = g_sq[b * 8 + g] * (1.0f / NG_) - mean * mean;
        float s = rsqrtf(var + 1e-5f) * gamma[c];
        sc[c] = s; tb[c] = beta[c] - mean * s;
    }
    __syncthreads();
#pragma unroll
    for (int i = 0; i < 16; i++) {
        int lin = i * 512 + tid, c = lin >> 5, px = (lin & 31) << 2;
        float4 v = *(const float4*)(x + ((size_t)(b * C_ + c)) * HW_ + p0 + px);
        float s = sc[c], t = tb[c];
        *(half2*)(Xs + c * LDX2 + px) = __floats2half2_rn(fmaf(v.x, s, t), fmaf(v.y, s, t));
        *(half2*)(Xs + c * LDX2 + px + 2) = __floats2half2_rn(fmaf(v.z, s, t), fmaf(v.w, s, t));
    }
    float acc[4][4][4];
    // ---- Q ----
    gemm_body<LDX2, 512>(g_Wh, xs, Wbuf, tid, lane, wo, wp, acc);
    stageW<512>(Wbuf, g_Wh + 65536, tid); CP_COMMIT();
#pragma unroll
    for (int m = 0; m < 4; m++) {
        int row = wo * 64 + m * 16 + (lane >> 2);
        float b0 = bq[row], b1 = bq[row + 8];
        size_t o0 = ((size_t)(b * C_ + row)) * HW_ + p0;
        size_t o1 = ((size_t)(b * C_ + row + 8)) * HW_ + p0;
#pragma unroll
        for (int n = 0; n < 4; n++) {
            int col = wp * 32 + n * 8 + (c2 << 1);
            *(half2*)(g_q + o0 + col) = __floats2half2_rn(elu1(acc[m][n][0] + b0), elu1(acc[m][n][1] + b0));
            *(half2*)(g_q + o1 + col) = __floats2half2_rn(elu1(acc[m][n][2] + b1), elu1(acc[m][n][3] + b1));
        }
    }
    // ---- K + fused ksum ----
    gemm_body<LDX2, 512>(g_Wh + 65536, xs, Wbuf, tid, lane, wo, wp, acc);
    stageW<512>(Wbuf, g_Wh + 131072, tid); CP_COMMIT();
#pragma unroll
    for (int m = 0; m < 4; m++) {
        int row = wo * 64 + m * 16 + (lane >> 2);
        float b0 = bk[row], b1 = bk[row + 8];
        size_t o0 = ((size_t)(b * C_ + row)) * HW_ + p0;
        size_t o1 = ((size_t)(b * C_ + row + 8)) * HW_ + p0;
        float s0 = 0.f, s1 = 0.f;
#pragma unroll
        for (int n = 0; n < 4; n++) {
            int col = wp * 32 + n * 8 + (c2 << 1);
            half2 h0 = __floats2half2_rn(elu1(acc[m][n][0] + b0), elu1(acc[m][n][1] + b0));
            half2 h1 = __floats2half2_rn(elu1(acc[m][n][2] + b1), elu1(acc[m][n][3] + b1));
            *(half2*)(g_k + o0 + col) = h0;
            *(half2*)(g_k + o1 + col) = h1;
            s0 += __low2float(h0) + __high2float(h0);
            s1 += __low2float(h1) + __high2float(h1);
        }
        s0 += __shfl_xor_sync(~0u, s0, 1); s0 += __shfl_xor_sync(~0u, s0, 2);
        s1 += __shfl_xor_sync(~0u, s1, 1); s1 += __shfl_xor_sync(~0u, s1, 2);
        if (c2 == 0) {
            atomicAdd(&g_ksum[b * C_ + row], s0);
            atomicAdd(&g_ksum[b * C_ + row + 8], s1);
        }
    }
    // ---- V ----
    gemm_body<LDX2, 512>(g_Wh + 131072, xs, Wbuf, tid, lane, wo, wp, acc);
#pragma unroll
    for (int m = 0; m < 4; m++) {
        int row = wo * 64 + m * 16 + (lane >> 2);
        float b0 = bv[row], b1 = bv[row + 8];
        size_t o0 = ((size_t)(b * C_ + row)) * HW_ + p0;
        size_t o1 = ((size_t)(b * C_ + row + 8)) * HW_ + p0;
#pragma unroll
        for (int n = 0; n < 4; n++) {
            int col = wp * 32 + n * 8 + (c2 << 1);
            *(half2*)(g_v + o0 + col) = __floats2half2_rn(acc[m][n][0] + b0, acc[m][n][1] + b0);
            *(half2*)(g_v + o1 + col) = __floats2half2_rn(acc[m][n][2] + b1, acc[m][n][3] + b1);
        }
    }
}

// ---------------- k_kv: 512 threads, 256x128 kv tiles, RED into g_kvn ----------------
__device__ __forceinline__ void kv_stage(__half* Kt, int b, int cv0, int p0, int tid) {
#pragma unroll
    for (int i = 0; i < 2; i++) {
        int lin = i * 512 + tid, row = lin >> 2, seg = lin & 3;
        cp16(Kt + row * LDWS + seg * 8, g_k + ((size_t)(b * C_ + row)) * HW_ + p0 + seg * 8);
    }
    {
        int row = tid >> 2, seg = tid & 3;
        cp16(Kt + 256 * LDWS + row * LDWS + seg * 8,
             g_v + ((size_t)(b * C_ + cv0 + row)) * HW_ + p0 + seg * 8);
    }
    CP_COMMIT();
}

__global__ void __launch_bounds__(512, 1) k_kv() {
    extern __shared__ __half smh[];
    const int TSZ = 384 * LDWS;   // k 256 rows + v 128 rows
    int s = blockIdx.x >> 1, cvt = blockIdx.x & 1, b = blockIdx.y;
    int cv0 = cvt * 128;
    int tid = threadIdx.x, lane = tid & 31, warp = tid >> 5;
    int wo = warp & 3, wp = warp >> 2, c2 = lane & 3;
    int rowA = lane & 15, colA = (lane & 16) >> 1;
    int rowB = (lane & 7) + ((lane & 16) >> 1), colB = lane & 8;
    float acc[4][4][4];
#pragma unroll
    for (int m = 0; m < 4; m++)
#pragma unroll
        for (int n = 0; n < 4; n++)
#pragma unroll
            for (int i = 0; i < 4; i++) acc[m][n][i] = 0.f;
    kv_stage(smh, b, cv0, s * 1024, tid);
#pragma unroll 1
    for (int ch = 0; ch < 32; ch++) {
        CP_WAIT0();
        __syncthreads();
        if (ch < 31) kv_stage(smh + ((ch + 1) & 1) * TSZ, b, cv0, s * 1024 + (ch + 1) * 32, tid);
        uint32_t kt = s2u(smh + (ch & 1) * TSZ);
        uint32_t vt = kt + 256 * LDWS * 2;
#pragma unroll
        for (int ks = 0; ks < 2; ks++) {
            uint32_t A[4][4];
#pragma unroll
            for (int m = 0; m < 4; m++)
                ldsm4(A[m], kt + ((wo * 64 + m * 16 + rowA) * LDWS + ks * 16 + colA) * 2);
            uint32_t Bv[2][4];
#pragma unroll
            for (int t = 0; t < 2; t++)
                ldsm4(Bv[t], vt + ((wp * 32 + t * 16 + rowB) * LDWS + ks * 16 + colB) * 2);
#pragma unroll
            for (int m = 0; m < 4; m++)
#pragma unroll
                for (int n = 0; n < 4; n++)
                    mma16(acc[m][n], A[m], Bv[n >> 1][(n & 1) * 2], Bv[n >> 1][(n & 1) * 2 + 1]);
        }
    }
    float* outp = g_kvn + (size_t)b * 65536;
#pragma unroll
    for (int m = 0; m < 4; m++) {
        int row = wo * 64 + m * 16 + (lane >> 2);
#pragma unroll
        for (int n = 0; n < 4; n++) {
            int col = cv0 + wp * 32 + n * 8 + (c2 << 1);
            red2(outp + row * 256 + col, acc[m][n][0], acc[m][n][1]);
            red2(outp + (row + 8) * 256 + col, acc[m][n][2], acc[m][n][3]);
        }
    }
}

__global__ void __launch_bounds__(256) k_red() {
    int gid = blockIdx.x * 256 + threadIdx.x;
    float4 v = *(float4*)(g_kvn + (size_t)gid * 4);
    int row = gid >> 6;
    float inv = 1.0f / (g_ksum[row] + 1e-6f);
    v.x *= inv; v.y *= inv; v.z *= inv; v.w *= inv;
    *(float4*)(g_kvn + (size_t)gid * 4) = v;
}

// ---------------- k_m: M = Wp @ kvn (256 thr, 64-wide) ----------------
__global__ void __launch_bounds__(256, 2) k_m() {
    extern __shared__ __half smh[];
    __half* Xs = smh;
    __half* Wbuf = smh + 256 * LDX1;
    int b = blockIdx.y, d0 = blockIdx.x * 64;
    int tid = threadIdx.x, lane = tid & 31, warp = tid >> 5;
    int wo = warp & 3, wp_ = warp >> 2, c2 = lane & 3;
    uint32_t xs = s2u(Xs);
    stageW<256>(Wbuf, g_Wh + 196608, tid); CP_COMMIT();
#pragma unroll
    for (int i = 0; i < 16; i++) {
        int lin = i * 256 + tid, c = lin >> 4, d4 = (lin & 15) << 2;
        float4 v = *(const float4*)(g_kvn + (size_t)(b * C_ + c) * C_ + d0 + d4);
        *(half2*)(Xs + c * LDX1 + d4) = __floats2half2_rn(v.x, v.y);
        *(half2*)(Xs + c * LDX1 + d4 + 2) = __floats2half2_rn(v.z, v.w);
    }
    float acc[4][4][4];
    gemm_body<LDX1, 256>(g_Wh + 196608, xs, Wbuf, tid, lane, wo, wp_, acc);
    __half* dst = g_M + (size_t)b * 65536;
#pragma unroll
    for (int m = 0; m < 4; m++) {
        int row = wo * 64 + m * 16 + (lane >> 2);
#pragma unroll
        for (int n = 0; n < 4; n++) {
            int col = d0 + wp_ * 32 + n * 8 + (c2 << 1);
            *(half2*)(dst + row * 256 + col) = __floats2half2_rn(acc[m][n][0], acc[m][n][1]);
            *(half2*)(dst + (row + 8) * 256 + col) = __floats2half2_rn(acc[m][n][2], acc[m][n][3]);
        }
    }
}

// ---------------- k_out: 512 threads, 256x128 tiles ----------------
__global__ void __launch_bounds__(512, 1) k_out(const float* __restrict__ x,
                                                const float* __restrict__ bp, float* __restrict__ out) {
    extern __shared__ __half smh[];
    __half* Xs = smh;
    __half* Wbuf = smh + 256 * LDX2;
    int b = blockIdx.y, p0 = blockIdx.x * 128;
    int tid = threadIdx.x, lane = tid & 31, warp = tid >> 5;
    int wo = warp & 3, wp = warp >> 2, c2 = lane & 3;
    uint32_t xs = s2u(Xs);
    const __half* Asrc = g_M + (size_t)b * 65536;
    stageW<512>(Wbuf, Asrc, tid); CP_COMMIT();
#pragma unroll
    for (int i = 0; i < 8; i++) {
        int lin = i * 512 + tid, d = lin >> 4, px = (lin & 15) << 3;
        uint4 v = *(const uint4*)(g_q + ((size_t)(b * C_ + d)) * HW_ + p0 + px);
        *(uint4*)(Xs + d * LDX2 + px) = v;
    }
    float acc[4][4][4];
    gemm_body<LDX2, 512>(Asrc, xs, Wbuf, tid, lane, wo, wp, acc);
#pragma unroll
    for (int m = 0; m < 4; m++) {
        int row = wo * 64 + m * 16 + (lane >> 2);
        float b0 = bp[row], b1 = bp[row + 8];
        size_t o0 = ((size_t)(b * C_ + row)) * HW_ + p0;
        size_t o1 = ((size_t)(b * C_ + row + 8)) * HW_ + p0;
#pragma unroll
        for (int n = 0; n < 4; n++) {
            int col = wp * 32 + n * 8 + (c2 << 1);
            float2 x0 = *(const float2*)(x + o0 + col);
            float2 x1 = *(const float2*)(x + o1 + col);
            *(float2*)(out + o0 + col) = make_float2(acc[m][n][0] + b0 + x0.x, acc[m][n][1] + b0 + x0.y);
            *(float2*)(out + o1 + col) = make_float2(acc[m][n][2] + b1 + x1.x, acc[m][n][3] + b1 + x1.y);
        }
    }
}

extern "C" void kernel_launch(void* const* d_in, const int* in_sizes, int n_in,
                              void* d_out, int out_size) {
    const float* x = (const float*)d_in[0];
    const float* gamma = (const float*)d_in[1];
    const float* beta = (const float*)d_in[2];
    const float* Wq = (const float*)d_in[3];
    const float* bq = (const float*)d_in[4];
    const float* Wk = (const float*)d_in[5];
    const float* bk = (const float*)d_in[6];
    const float* Wv = (const float*)d_in[7];
    const float* bv = (const float*)d_in[8];
    const float* Wp = (const float*)d_in[9];
    const float* bp = (const float*)d_in[10];
    float* out = (float*)d_out;

    const int SMEM_QKV = (256 * LDX2 + 2 * SZW) * 2 + 2048;  // 112640 B
    const int SMEM_OUT = (256 * LDX2 + 2 * SZW) * 2;         // 110592 B
    const int SMEM_M = (256 * LDX1 + 2 * SZW) * 2;           // 77824 B
    const int SMEM_KV = 2 * 384 * LDWS * 2;                   // 61440 B
    cudaFuncSetAttribute(k_qkv, cudaFuncAttributeMaxDynamicSharedMemorySize, SMEM_QKV);
    cudaFuncSetAttribute(k_out, cudaFuncAttributeMaxDynamicSharedMemorySize, SMEM_OUT);
    cudaFuncSetAttribute(k_m, cudaFuncAttributeMaxDynamicSharedMemorySize, SMEM_M);
    cudaFuncSetAttribute(k_kv, cudaFuncAttributeMaxDynamicSharedMemorySize, SMEM_KV);

    k0_zero<<<512, 256>>>();
    k_prep<<<256, 256>>>(Wq, Wk, Wv, Wp);
    k_stats<<<dim3(16, 64), 256>>>(x);
    k_qkv<<<dim3(128, 8), 512, SMEM_QKV>>>(x, gamma, beta, bq, bk, bv);
    k_kv<<<dim3(32, 8), 512, SMEM_KV>>>();
    k_red<<<512, 256>>>();
    k_m<<<dim3(4, 8), 256, SMEM_M>>>();
    k_out<<<dim3(128, 8), 512, SMEM_OUT>>>(x, bp, out);
}

// round 13
// speedup vs baseline: 1.0631x; 1.0631x over previous
#include <cuda_runtime.h>
#include <cuda_fp16.h>
#include <cstdint>

#define B_   8
#define C_   256
#define HW_  16384
#define NG_  524288.0f
#define LDXS 72        // Xs row pad (halves), 64-px tiles
#define LDW2 72        // W chunk row pad (halves), 64-wide chunks; 36 words mod 32 = 4 -> conflict-free
#define SZW2 (256 * LDW2)

// scratch (device globals; allocation APIs forbidden)
__device__ __half g_q[(size_t)B_ * C_ * HW_];
__device__ __half g_k[(size_t)B_ * C_ * HW_];
__device__ __half g_v[(size_t)B_ * C_ * HW_];
__device__ float  g_kvn[B_ * C_ * C_];
__device__ __half g_M[B_ * C_ * C_];
__device__ float  g_ksum[B_ * C_];
__device__ float  g_sum[B_ * 8];
__device__ float  g_sq[B_ * 8];
__device__ __half g_Wh[4 * 65536];   // fp16 Wq,Wk,Wv,Wp row-major [o][c]

__device__ __forceinline__ float elu1(float x) { return x > 0.f ? x + 1.f : __expf(x); }
__device__ __forceinline__ uint32_t s2u(const void* p) { return (uint32_t)__cvta_generic_to_shared(p); }
__device__ __forceinline__ void mma16(float c[4], const uint32_t a[4], const uint32_t b0, const uint32_t b1) {
    asm volatile("mma.sync.aligned.m16n8k16.row.col.f32.f16.f16.f32 "
        "{%0,%1,%2,%3},{%4,%5,%6,%7},{%8,%9},{%0,%1,%2,%3};\n"
        : "+f"(c[0]), "+f"(c[1]), "+f"(c[2]), "+f"(c[3])
        : "r"(a[0]), "r"(a[1]), "r"(a[2]), "r"(a[3]), "r"(b0), "r"(b1));
}
__device__ __forceinline__ void ldsm4(uint32_t r[4], uint32_t addr) {
    asm volatile("ldmatrix.sync.aligned.m8n8.x4.shared.b16 {%0,%1,%2,%3}, [%4];"
        : "=r"(r[0]), "=r"(r[1]), "=r"(r[2]), "=r"(r[3]) : "r"(addr));
}
__device__ __forceinline__ void ldsm4t(uint32_t r[4], uint32_t addr) {
    asm volatile("ldmatrix.sync.aligned.m8n8.x4.trans.shared.b16 {%0,%1,%2,%3}, [%4];"
        : "=r"(r[0]), "=r"(r[1]), "=r"(r[2]), "=r"(r[3]) : "r"(addr));
}
__device__ __forceinline__ void cp16(__half* dst, const __half* src) {
    asm volatile("cp.async.ca.shared.global [%0], [%1], 16;\n" :: "r"(s2u(dst)), "l"(src));
}
__device__ __forceinline__ void red2(float* addr, float a, float b) {
    asm volatile("red.global.add.v2.f32 [%0], {%1, %2};" :: "l"(addr), "f"(a), "f"(b) : "memory");
}
#define CP_COMMIT() asm volatile("cp.async.commit_group;\n")
#define CP_WAIT0()  asm volatile("cp.async.wait_group 0;\n")

// stage a 256-row x 64-half W chunk (gmem row stride 256 halves)
__device__ __forceinline__ void stageW64(__half* buf, const __half* src, int tid) {
#pragma unroll
    for (int i = 0; i < 8; i++) {
        int lin = i * 256 + tid, r = lin >> 3, s = lin & 7;
        cp16(buf + r * LDW2 + s * 8, src + (size_t)r * 256 + s * 8);
    }
}

// gemm body: chunk 0 pre-staged+committed by caller. 4 chunks of 64, double buffer,
// ONE sync/chunk, stage AFTER sync (race-free).
__device__ __forceinline__ void gemm_body(const __half* __restrict__ Wg, uint32_t xs,
                                          __half* Wbuf, int tid, int lane, int wo, int wp,
                                          float acc[4][4][4]) {
#pragma unroll
    for (int m = 0; m < 4; m++)
#pragma unroll
        for (int n = 0; n < 4; n++)
#pragma unroll
            for (int i = 0; i < 4; i++) acc[m][n][i] = 0.f;
    uint32_t wbu = s2u(Wbuf);
    int rowA = lane & 15, colA = (lane & 16) >> 1;
    int rowB = (lane & 7) + (lane & 8), colB = (lane & 16) >> 1;
#pragma unroll 1
    for (int kc = 0; kc < 4; kc++) {
        CP_WAIT0();
        __syncthreads();
        if (kc < 3) { stageW64(Wbuf + ((kc + 1) & 1) * SZW2, Wg + (kc + 1) * 64, tid); CP_COMMIT(); }
        uint32_t wcb = wbu + ((kc & 1) * SZW2) * 2;
#pragma unroll
        for (int ks = 0; ks < 4; ks++) {
            uint32_t A[4][4];
#pragma unroll
            for (int m = 0; m < 4; m++)
                ldsm4(A[m], wcb + ((wo * 64 + m * 16 + rowA) * LDW2 + ks * 16 + colA) * 2);
            uint32_t Bv[2][4];
            int kg = kc * 64 + ks * 16;
#pragma unroll
            for (int t = 0; t < 2; t++)
                ldsm4t(Bv[t], xs + ((kg + rowB) * LDXS + wp * 32 + t * 16 + colB) * 2);
#pragma unroll
            for (int m = 0; m < 4; m++)
#pragma unroll
                for (int n = 0; n < 4; n++)
                    mma16(acc[m][n], A[m], Bv[n >> 1][(n & 1) * 2], Bv[n >> 1][(n & 1) * 2 + 1]);
        }
    }
}

// ---------------- small kernels ----------------
__global__ void k0_zero() {
    int gid = blockIdx.x * 256 + threadIdx.x;
    *(float4*)(g_kvn + (size_t)gid * 4) = make_float4(0.f, 0.f, 0.f, 0.f);
    if (gid < B_ * C_) g_ksum[gid] = 0.f;
    if (gid < 64) { g_sum[gid] = 0.f; g_sq[gid] = 0.f; }
}
__global__ void k_prep(const float* __restrict__ Wq, const float* __restrict__ Wk,
                       const float* __restrict__ Wv, const float* __restrict__ Wp) {
    int i = blockIdx.x * 256 + threadIdx.x;
    g_Wh[i] = __float2half_rn(Wq[i]);
    g_Wh[65536 + i] = __float2half_rn(Wk[i]);
    g_Wh[131072 + i] = __float2half_rn(Wv[i]);
    g_Wh[196608 + i] = __float2half_rn(Wp[i]);
}
__global__ void __launch_bounds__(256) k_stats(const float* __restrict__ x) {
    int bg = blockIdx.y;
    const float* base = x + (size_t)bg * 524288 + blockIdx.x * 32768;
    int tid = threadIdx.x, lane = tid & 31, warp = tid >> 5;
    float s = 0.f, sq = 0.f;
    for (int i = tid; i < 8192; i += 256) {
        float4 v = *(const float4*)(base + i * 4);
        s += v.x + v.y + v.z + v.w;
        sq = fmaf(v.x, v.x, sq); sq = fmaf(v.y, v.y, sq);
        sq = fmaf(v.z, v.z, sq); sq = fmaf(v.w, v.w, sq);
    }
#pragma unroll
    for (int o = 16; o > 0; o >>= 1) {
        s += __shfl_xor_sync(~0u, s, o); sq += __shfl_xor_sync(~0u, sq, o);
    }
    __shared__ float rs[8], rq[8];
    if (lane == 0) { rs[warp] = s; rq[warp] = sq; }
    __syncthreads();
    if (tid == 0) {
        float S = 0.f, Q = 0.f;
#pragma unroll
        for (int i = 0; i < 8; i++) { S += rs[i]; Q += rq[i]; }
        atomicAdd(&g_sum[bg], S); atomicAdd(&g_sq[bg], Q);
    }
}

// ---------------- k_qkv: GN + Q/K/V convs + ksum ----------------
__global__ void __launch_bounds__(256, 2) k_qkv(
    const float* __restrict__ x, const float* __restrict__ gamma, const float* __restrict__ beta,
    const float* __restrict__ bq, const float* __restrict__ bk, const float* __restrict__ bv) {
    extern __shared__ __half smh[];
    __half* Xs = smh;                          // [256 k][LDXS]
    __half* Wbuf = smh + 256 * LDXS;           // 2 x SZW2
    float* sc = (float*)(smh + 256 * LDXS + 2 * SZW2);
    float* tb = sc + 256;
    int b = blockIdx.y, p0 = blockIdx.x * 64;
    int tid = threadIdx.x, lane = tid & 31, warp = tid >> 5;
    int wo = warp & 3, wp = warp >> 2, c2 = lane & 3;
    uint32_t xs = s2u(Xs);
    stageW64(Wbuf, g_Wh, tid); CP_COMMIT();
    {
        int c = tid, g = c >> 5;
        float mean = g_sum[b * 8 + g] * (1.0f / NG_);
        float var = g_sq[b * 8 + g] * (1.0f / NG_) - mean * mean;
        float s = rsqrtf(var + 1e-5f) * gamma[c];
        sc[c] = s; tb[c] = beta[c] - mean * s;
    }
    __syncthreads();
#pragma unroll
    for (int i = 0; i < 16; i++) {
        int lin = i * 256 + tid, c = lin >> 4, px = (lin & 15) << 2;
        float4 v = *(const float4*)(x + ((size_t)(b * C_ + c)) * HW_ + p0 + px);
        float s = sc[c], t = tb[c];
        *(half2*)(Xs + c * LDXS + px) = __floats2half2_rn(fmaf(v.x, s, t), fmaf(v.y, s, t));
        *(half2*)(Xs + c * LDXS + px + 2) = __floats2half2_rn(fmaf(v.z, s, t), fmaf(v.w, s, t));
    }
    float acc[4][4][4];
    // ---- Q ----
    gemm_body(g_Wh, xs, Wbuf, tid, lane, wo, wp, acc);
    stageW64(Wbuf, g_Wh + 65536, tid); CP_COMMIT();   // prefetch Wk chunk0 (overlaps epilogue)
#pragma unroll
    for (int m = 0; m < 4; m++) {
        int row = wo * 64 + m * 16 + (lane >> 2);
        float b0 = bq[row], b1 = bq[row + 8];
        size_t o0 = ((size_t)(b * C_ + row)) * HW_ + p0;
        size_t o1 = ((size_t)(b * C_ + row + 8)) * HW_ + p0;
#pragma unroll
        for (int n = 0; n < 4; n++) {
            int col = wp * 32 + n * 8 + (c2 << 1);
            *(half2*)(g_q + o0 + col) = __floats2half2_rn(elu1(acc[m][n][0] + b0), elu1(acc[m][n][1] + b0));
            *(half2*)(g_q + o1 + col) = __floats2half2_rn(elu1(acc[m][n][2] + b1), elu1(acc[m][n][3] + b1));
        }
    }
    // ---- K + fused ksum ----
    gemm_body(g_Wh + 65536, xs, Wbuf, tid, lane, wo, wp, acc);
    stageW64(Wbuf, g_Wh + 131072, tid); CP_COMMIT();  // prefetch Wv chunk0
#pragma unroll
    for (int m = 0; m < 4; m++) {
        int row = wo * 64 + m * 16 + (lane >> 2);
        float b0 = bk[row], b1 = bk[row + 8];
        size_t o0 = ((size_t)(b * C_ + row)) * HW_ + p0;
        size_t o1 = ((size_t)(b * C_ + row + 8)) * HW_ + p0;
        float s0 = 0.f, s1 = 0.f;
#pragma unroll
        for (int n = 0; n < 4; n++) {
            int col = wp * 32 + n * 8 + (c2 << 1);
            half2 h0 = __floats2half2_rn(elu1(acc[m][n][0] + b0), elu1(acc[m][n][1] + b0));
            half2 h1 = __floats2half2_rn(elu1(acc[m][n][2] + b1), elu1(acc[m][n][3] + b1));
            *(half2*)(g_k + o0 + col) = h0;
            *(half2*)(g_k + o1 + col) = h1;
            s0 += __low2float(h0) + __high2float(h0);
            s1 += __low2float(h1) + __high2float(h1);
        }
        s0 += __shfl_xor_sync(~0u, s0, 1); s0 += __shfl_xor_sync(~0u, s0, 2);
        s1 += __shfl_xor_sync(~0u, s1, 1); s1 += __shfl_xor_sync(~0u, s1, 2);
        if (c2 == 0) {
            atomicAdd(&g_ksum[b * C_ + row], s0);
            atomicAdd(&g_ksum[b * C_ + row + 8], s1);
        }
    }
    // ---- V ----
    gemm_body(g_Wh + 131072, xs, Wbuf, tid, lane, wo, wp, acc);
#pragma unroll
    for (int m = 0; m < 4; m++) {
        int row = wo * 64 + m * 16 + (lane >> 2);
        float b0 = bv[row], b1 = bv[row + 8];
        size_t o0 = ((size_t)(b * C_ + row)) * HW_ + p0;
        size_t o1 = ((size_t)(b * C_ + row + 8)) * HW_ + p0;
#pragma unroll
        for (int n = 0; n < 4; n++) {
            int col = wp * 32 + n * 8 + (c2 << 1);
            *(half2*)(g_v + o0 + col) = __floats2half2_rn(acc[m][n][0] + b0, acc[m][n][1] + b0);
            *(half2*)(g_v + o1 + col) = __floats2half2_rn(acc[m][n][2] + b1, acc[m][n][3] + b1);
        }
    }
}

// ---------------- k_kv: split-K, 64-px chunks, RED into g_kvn ----------------
__device__ __forceinline__ void kv_stage(__half* Kt, int b, int cv0, int p0, int tid) {
#pragma unroll
    for (int i = 0; i < 8; i++) {
        int lin = i * 256 + tid, row = lin >> 3, seg = lin & 7;
        cp16(Kt + row * LDW2 + seg * 8, g_k + ((size_t)(b * C_ + row)) * HW_ + p0 + seg * 8);
    }
#pragma unroll
    for (int i = 0; i < 2; i++) {
        int lin = i * 256 + tid, row = lin >> 3, seg = lin & 7;
        cp16(Kt + 256 * LDW2 + row * LDW2 + seg * 8,
             g_v + ((size_t)(b * C_ + cv0 + row)) * HW_ + p0 + seg * 8);
    }
    CP_COMMIT();
}

__global__ void __launch_bounds__(256, 2) k_kv() {
    extern __shared__ __half smh[];
    const int TSZ = 320 * LDW2;   // K 256 rows + V 64 rows
    int s = blockIdx.x >> 2, cvt = blockIdx.x & 3, b = blockIdx.y;
    int cv0 = cvt * 64;
    int tid = threadIdx.x, lane = tid & 31, warp = tid >> 5;
    int wo = warp & 3, wp = warp >> 2, c2 = lane & 3;
    int rowA = lane & 15, colA = (lane & 16) >> 1;
    int rowB = (lane & 7) + ((lane & 16) >> 1), colB = lane & 8;
    float acc[4][4][4];
#pragma unroll
    for (int m = 0; m < 4; m++)
#pragma unroll
        for (int n = 0; n < 4; n++)
#pragma unroll
            for (int i = 0; i < 4; i++) acc[m][n][i] = 0.f;
    kv_stage(smh, b, cv0, s * 1024, tid);
#pragma unroll 1
    for (int ch = 0; ch < 16; ch++) {
        CP_WAIT0();
        __syncthreads();
        if (ch < 15) kv_stage(smh + ((ch + 1) & 1) * TSZ, b, cv0, s * 1024 + (ch + 1) * 64, tid);
        uint32_t kt = s2u(smh + (ch & 1) * TSZ);
        uint32_t vt = kt + 256 * LDW2 * 2;
#pragma unroll
        for (int ks = 0; ks < 4; ks++) {
            uint32_t A[4][4];
#pragma unroll
            for (int m = 0; m < 4; m++)
                ldsm4(A[m], kt + ((wo * 64 + m * 16 + rowA) * LDW2 + ks * 16 + colA) * 2);
            uint32_t Bv[2][4];
#pragma unroll
            for (int t = 0; t < 2; t++)
                ldsm4(Bv[t], vt + ((wp * 32 + t * 16 + rowB) * LDW2 + ks * 16 + colB) * 2);
#pragma unroll
            for (int m = 0; m < 4; m++)
#pragma unroll
                for (int n = 0; n < 4; n++)
                    mma16(acc[m][n], A[m], Bv[n >> 1][(n & 1) * 2], Bv[n >> 1][(n & 1) * 2 + 1]);
        }
    }
    float* outp = g_kvn + (size_t)b * 65536;
#pragma unroll
    for (int m = 0; m < 4; m++) {
        int row = wo * 64 + m * 16 + (lane >> 2);
#pragma unroll
        for (int n = 0; n < 4; n++) {
            int col = cv0 + wp * 32 + n * 8 + (c2 << 1);
            red2(outp + row * 256 + col, acc[m][n][0], acc[m][n][1]);
            red2(outp + (row + 8) * 256 + col, acc[m][n][2], acc[m][n][3]);
        }
    }
}

__global__ void __launch_bounds__(256) k_red() {
    int gid = blockIdx.x * 256 + threadIdx.x;
    float4 v = *(float4*)(g_kvn + (size_t)gid * 4);
    int row = gid >> 6;
    float inv = 1.0f / (g_ksum[row] + 1e-6f);
    v.x *= inv; v.y *= inv; v.z *= inv; v.w *= inv;
    *(float4*)(g_kvn + (size_t)gid * 4) = v;
}

// ---------------- k_m: M = Wp @ kvn ----------------
__global__ void __launch_bounds__(256, 2) k_m() {
    extern __shared__ __half smh[];
    __half* Xs = smh;
    __half* Wbuf = smh + 256 * LDXS;
    int b = blockIdx.y, d0 = blockIdx.x * 64;
    int tid = threadIdx.x, lane = tid & 31, warp = tid >> 5;
    int wo = warp & 3, wp_ = warp >> 2, c2 = lane & 3;
    uint32_t xs = s2u(Xs);
    stageW64(Wbuf, g_Wh + 196608, tid); CP_COMMIT();
#pragma unroll
    for (int i = 0; i < 16; i++) {
        int lin = i * 256 + tid, c = lin >> 4, d4 = (lin & 15) << 2;
        float4 v = *(const float4*)(g_kvn + (size_t)(b * C_ + c) * C_ + d0 + d4);
        *(half2*)(Xs + c * LDXS + d4) = __floats2half2_rn(v.x, v.y);
        *(half2*)(Xs + c * LDXS + d4 + 2) = __floats2half2_rn(v.z, v.w);
    }
    float acc[4][4][4];
    gemm_body(g_Wh + 196608, xs, Wbuf, tid, lane, wo, wp_, acc);
    __half* dst = g_M + (size_t)b * 65536;
#pragma unroll
    for (int m = 0; m < 4; m++) {
        int row = wo * 64 + m * 16 + (lane >> 2);
#pragma unroll
        for (int n = 0; n < 4; n++) {
            int col = d0 + wp_ * 32 + n * 8 + (c2 << 1);
            *(half2*)(dst + row * 256 + col) = __floats2half2_rn(acc[m][n][0], acc[m][n][1]);
            *(half2*)(dst + (row + 8) * 256 + col) = __floats2half2_rn(acc[m][n][2], acc[m][n][3]);
        }
    }
}

// ---------------- k_out: out = M @ q + bp + x ----------------
__global__ void __launch_bounds__(256, 2) k_out(const float* __restrict__ x,
                                                const float* __restrict__ bp, float* __restrict__ out) {
    extern __shared__ __half smh[];
    __half* Xs = smh;
    __half* Wbuf = smh + 256 * LDXS;
    int b = blockIdx.y, p0 = blockIdx.x * 64;
    int tid = threadIdx.x, lane = tid & 31, warp = tid >> 5;
    int wo = warp & 3, wp = warp >> 2, c2 = lane & 3;
    uint32_t xs = s2u(Xs);
    const __half* Asrc = g_M + (size_t)b * 65536;
    stageW64(Wbuf, Asrc, tid); CP_COMMIT();
#pragma unroll
    for (int i = 0; i < 8; i++) {
        int lin = i * 256 + tid, d = lin >> 3, px = (lin & 7) << 3;
        uint4 v = *(const uint4*)(g_q + ((size_t)(b * C_ + d)) * HW_ + p0 + px);
        *(uint4*)(Xs + d * LDXS + px) = v;
    }
    float acc[4][4][4];
    gemm_body(Asrc, xs, Wbuf, tid, lane, wo, wp, acc);
#pragma unroll
    for (int m = 0; m < 4; m++) {
        int row = wo * 64 + m * 16 + (lane >> 2);
        float b0 = bp[row], b1 = bp[row + 8];
        size_t o0 = ((size_t)(b * C_ + row)) * HW_ + p0;
        size_t o1 = ((size_t)(b * C_ + row + 8)) * HW_ + p0;
#pragma unroll
        for (int n = 0; n < 4; n++) {
            int col = wp * 32 + n * 8 + (c2 << 1);
            float2 x0 = *(const float2*)(x + o0 + col);
            float2 x1 = *(const float2*)(x + o1 + col);
            *(float2*)(out + o0 + col) = make_float2(acc[m][n][0] + b0 + x0.x, acc[m][n][1] + b0 + x0.y);
            *(float2*)(out + o1 + col) = make_float2(acc[m][n][2] + b1 + x1.x, acc[m][n][3] + b1 + x1.y);
        }
    }
}

extern "C" void kernel_launch(void* const* d_in, const int* in_sizes, int n_in,
                              void* d_out, int out_size) {
    const float* x = (const float*)d_in[0];
    const float* gamma = (const float*)d_in[1];
    const float* beta = (const float*)d_in[2];
    const float* Wq = (const float*)d_in[3];
    const float* bq = (const float*)d_in[4];
    const float* Wk = (const float*)d_in[5];
    const float* bk = (const float*)d_in[6];
    const float* Wv = (const float*)d_in[7];
    const float* bv = (const float*)d_in[8];
    const float* Wp = (const float*)d_in[9];
    const float* bp = (const float*)d_in[10];
    float* out = (float*)d_out;

    const int SMEM_QKV = (256 * LDXS + 2 * SZW2) * 2 + 2048;  // 112640 B -> 2 CTAs/SM
    const int SMEM_GEMM = (256 * LDXS + 2 * SZW2) * 2;        // 110592 B
    const int SMEM_KV = 2 * 320 * LDW2 * 2;                    // 92160 B
    cudaFuncSetAttribute(k_qkv, cudaFuncAttributeMaxDynamicSharedMemorySize, SMEM_QKV);
    cudaFuncSetAttribute(k_m, cudaFuncAttributeMaxDynamicSharedMemorySize, SMEM_GEMM);
    cudaFuncSetAttribute(k_out, cudaFuncAttributeMaxDynamicSharedMemorySize, SMEM_GEMM);
    cudaFuncSetAttribute(k_kv, cudaFuncAttributeMaxDynamicSharedMemorySize, SMEM_KV);

    k0_zero<<<512, 256>>>();
    k_prep<<<256, 256>>>(Wq, Wk, Wv, Wp);
    k_stats<<<dim3(16, 64), 256>>>(x);
    k_qkv<<<dim3(256, 8), 256, SMEM_QKV>>>(x, gamma, beta, bq, bk, bv);
    k_kv<<<dim3(64, 8), 256, SMEM_KV>>>();
    k_red<<<512, 256>>>();
    k_m<<<dim3(4, 8), 256, SMEM_GEMM>>>();
    k_out<<<dim3(256, 8), 256, SMEM_GEMM>>>(x, bp, out);
}

// round 14
// speedup vs baseline: 1.0899x; 1.0252x over previous
#include <cuda_runtime.h>
#include <cuda_fp16.h>
#include <cstdint>

#define B_   8
#define C_   256
#define HW_  16384
#define NG_  524288.0f
#define LDXS 72        // Xs row pad (halves), 64-px tiles
#define LDW2 72        // W chunk row pad (halves), 64-wide chunks
#define SZW2 (256 * LDW2)

// scratch (device globals; allocation APIs forbidden)
__device__ __half g_q[(size_t)B_ * C_ * HW_];
__device__ __half g_k[(size_t)B_ * C_ * HW_];
__device__ __half g_v[(size_t)B_ * C_ * HW_];
__device__ float  g_kvn[B_ * C_ * C_];
__device__ __half g_M[B_ * C_ * C_];
__device__ float  g_ksum[B_ * C_];
__device__ float  g_sum[B_ * 8];
__device__ float  g_sq[B_ * 8];
__device__ __half g_Wh[4 * 65536];   // fp16 Wq,Wk,Wv,Wp row-major [o][c]

__device__ __forceinline__ float elu1(float x) { return x > 0.f ? x + 1.f : __expf(x); }
__device__ __forceinline__ uint32_t s2u(const void* p) { return (uint32_t)__cvta_generic_to_shared(p); }
__device__ __forceinline__ void mma16(float c[4], const uint32_t a[4], const uint32_t b0, const uint32_t b1) {
    asm volatile("mma.sync.aligned.m16n8k16.row.col.f32.f16.f16.f32 "
        "{%0,%1,%2,%3},{%4,%5,%6,%7},{%8,%9},{%0,%1,%2,%3};\n"
        : "+f"(c[0]), "+f"(c[1]), "+f"(c[2]), "+f"(c[3])
        : "r"(a[0]), "r"(a[1]), "r"(a[2]), "r"(a[3]), "r"(b0), "r"(b1));
}
__device__ __forceinline__ void ldsm4(uint32_t r[4], uint32_t addr) {
    asm volatile("ldmatrix.sync.aligned.m8n8.x4.shared.b16 {%0,%1,%2,%3}, [%4];"
        : "=r"(r[0]), "=r"(r[1]), "=r"(r[2]), "=r"(r[3]) : "r"(addr));
}
__device__ __forceinline__ void ldsm4t(uint32_t r[4], uint32_t addr) {
    asm volatile("ldmatrix.sync.aligned.m8n8.x4.trans.shared.b16 {%0,%1,%2,%3}, [%4];"
        : "=r"(r[0]), "=r"(r[1]), "=r"(r[2]), "=r"(r[3]) : "r"(addr));
}
__device__ __forceinline__ void cp16(__half* dst, const __half* src) {
    asm volatile("cp.async.ca.shared.global [%0], [%1], 16;\n" :: "r"(s2u(dst)), "l"(src));
}
__device__ __forceinline__ void red2(float* addr, float a, float b) {
    asm volatile("red.global.add.v2.f32 [%0], {%1, %2};" :: "l"(addr), "f"(a), "f"(b) : "memory");
}
#define CP_COMMIT() asm volatile("cp.async.commit_group;\n")
#define CP_WAIT0()  asm volatile("cp.async.wait_group 0;\n")

// stage a 256-row x 64-half W chunk (gmem row stride 256 halves)
__device__ __forceinline__ void stageW64(__half* buf, const __half* src, int tid) {
#pragma unroll
    for (int i = 0; i < 8; i++) {
        int lin = i * 256 + tid, r = lin >> 3, s = lin & 7;
        cp16(buf + r * LDW2 + s * 8, src + (size_t)r * 256 + s * 8);
    }
}

// gemm body: chunk 0 pre-staged+committed by caller. 4 chunks of 64, double buffer,
// ONE sync/chunk, stage AFTER sync (race-free).
__device__ __forceinline__ void gemm_body(const __half* __restrict__ Wg, uint32_t xs,
                                          __half* Wbuf, int tid, int lane, int wo, int wp,
                                          float acc[4][4][4]) {
#pragma unroll
    for (int m = 0; m < 4; m++)
#pragma unroll
        for (int n = 0; n < 4; n++)
#pragma unroll
            for (int i = 0; i < 4; i++) acc[m][n][i] = 0.f;
    uint32_t wbu = s2u(Wbuf);
    int rowA = lane & 15, colA = (lane & 16) >> 1;
    int rowB = (lane & 7) + (lane & 8), colB = (lane & 16) >> 1;
#pragma unroll 1
    for (int kc = 0; kc < 4; kc++) {
        CP_WAIT0();
        __syncthreads();
        if (kc < 3) { stageW64(Wbuf + ((kc + 1) & 1) * SZW2, Wg + (kc + 1) * 64, tid); CP_COMMIT(); }
        uint32_t wcb = wbu + ((kc & 1) * SZW2) * 2;
#pragma unroll
        for (int ks = 0; ks < 4; ks++) {
            uint32_t A[4][4];
#pragma unroll
            for (int m = 0; m < 4; m++)
                ldsm4(A[m], wcb + ((wo * 64 + m * 16 + rowA) * LDW2 + ks * 16 + colA) * 2);
            uint32_t Bv[2][4];
            int kg = kc * 64 + ks * 16;
#pragma unroll
            for (int t = 0; t < 2; t++)
                ldsm4t(Bv[t], xs + ((kg + rowB) * LDXS + wp * 32 + t * 16 + colB) * 2);
#pragma unroll
            for (int m = 0; m < 4; m++)
#pragma unroll
                for (int n = 0; n < 4; n++)
                    mma16(acc[m][n], A[m], Bv[n >> 1][(n & 1) * 2], Bv[n >> 1][(n & 1) * 2 + 1]);
        }
    }
}

// ---------------- small kernels ----------------
__global__ void k0_zero() {
    int gid = blockIdx.x * 256 + threadIdx.x;
    *(float4*)(g_kvn + (size_t)gid * 4) = make_float4(0.f, 0.f, 0.f, 0.f);
    if (gid < B_ * C_) g_ksum[gid] = 0.f;
    if (gid < 64) { g_sum[gid] = 0.f; g_sq[gid] = 0.f; }
}
__global__ void k_prep(const float* __restrict__ Wq, const float* __restrict__ Wk,
                       const float* __restrict__ Wv, const float* __restrict__ Wp) {
    int i = blockIdx.x * 256 + threadIdx.x;
    g_Wh[i] = __float2half_rn(Wq[i]);
    g_Wh[65536 + i] = __float2half_rn(Wk[i]);
    g_Wh[131072 + i] = __float2half_rn(Wv[i]);
    g_Wh[196608 + i] = __float2half_rn(Wp[i]);
}
__global__ void __launch_bounds__(256) k_stats(const float* __restrict__ x) {
    int bg = blockIdx.y;
    const float* base = x + (size_t)bg * 524288 + blockIdx.x * 32768;
    int tid = threadIdx.x, lane = tid & 31, warp = tid >> 5;
    float s = 0.f, sq = 0.f;
    for (int i = tid; i < 8192; i += 256) {
        float4 v = *(const float4*)(base + i * 4);
        s += v.x + v.y + v.z + v.w;
        sq = fmaf(v.x, v.x, sq); sq = fmaf(v.y, v.y, sq);
        sq = fmaf(v.z, v.z, sq); sq = fmaf(v.w, v.w, sq);
    }
#pragma unroll
    for (int o = 16; o > 0; o >>= 1) {
        s += __shfl_xor_sync(~0u, s, o); sq += __shfl_xor_sync(~0u, sq, o);
    }
    __shared__ float rs[8], rq[8];
    if (lane == 0) { rs[warp] = s; rq[warp] = sq; }
    __syncthreads();
    if (tid == 0) {
        float S = 0.f, Q = 0.f;
#pragma unroll
        for (int i = 0; i < 8; i++) { S += rs[i]; Q += rq[i]; }
        atomicAdd(&g_sum[bg], S); atomicAdd(&g_sq[bg], Q);
    }
}

// ---------------- k_qkv: GN + Q/K/V convs + ksum (unchanged from R13) ----------------
__global__ void __launch_bounds__(256, 2) k_qkv(
    const float* __restrict__ x, const float* __restrict__ gamma, const float* __restrict__ beta,
    const float* __restrict__ bq, const float* __restrict__ bk, const float* __restrict__ bv) {
    extern __shared__ __half smh[];
    __half* Xs = smh;
    __half* Wbuf = smh + 256 * LDXS;
    float* sc = (float*)(smh + 256 * LDXS + 2 * SZW2);
    float* tb = sc + 256;
    int b = blockIdx.y, p0 = blockIdx.x * 64;
    int tid = threadIdx.x, lane = tid & 31, warp = tid >> 5;
    int wo = warp & 3, wp = warp >> 2, c2 = lane & 3;
    uint32_t xs = s2u(Xs);
    stageW64(Wbuf, g_Wh, tid); CP_COMMIT();
    {
        int c = tid, g = c >> 5;
        float mean = g_sum[b * 8 + g] * (1.0f / NG_);
        float var = g_sq[b * 8 + g] * (1.0f / NG_) - mean * mean;
        float s = rsqrtf(var + 1e-5f) * gamma[c];
        sc[c] = s; tb[c] = beta[c] - mean * s;
    }
    __syncthreads();
#pragma unroll
    for (int i = 0; i < 16; i++) {
        int lin = i * 256 + tid, c = lin >> 4, px = (lin & 15) << 2;
        float4 v = *(const float4*)(x + ((size_t)(b * C_ + c)) * HW_ + p0 + px);
        float s = sc[c], t = tb[c];
        *(half2*)(Xs + c * LDXS + px) = __floats2half2_rn(fmaf(v.x, s, t), fmaf(v.y, s, t));
        *(half2*)(Xs + c * LDXS + px + 2) = __floats2half2_rn(fmaf(v.z, s, t), fmaf(v.w, s, t));
    }
    float acc[4][4][4];
    // ---- Q ----
    gemm_body(g_Wh, xs, Wbuf, tid, lane, wo, wp, acc);
    stageW64(Wbuf, g_Wh + 65536, tid); CP_COMMIT();
#pragma unroll
    for (int m = 0; m < 4; m++) {
        int row = wo * 64 + m * 16 + (lane >> 2);
        float b0 = bq[row], b1 = bq[row + 8];
        size_t o0 = ((size_t)(b * C_ + row)) * HW_ + p0;
        size_t o1 = ((size_t)(b * C_ + row + 8)) * HW_ + p0;
#pragma unroll
        for (int n = 0; n < 4; n++) {
            int col = wp * 32 + n * 8 + (c2 << 1);
            *(half2*)(g_q + o0 + col) = __floats2half2_rn(elu1(acc[m][n][0] + b0), elu1(acc[m][n][1] + b0));
            *(half2*)(g_q + o1 + col) = __floats2half2_rn(elu1(acc[m][n][2] + b1), elu1(acc[m][n][3] + b1));
        }
    }
    // ---- K + fused ksum ----
    gemm_body(g_Wh + 65536, xs, Wbuf, tid, lane, wo, wp, acc);
    stageW64(Wbuf, g_Wh + 131072, tid); CP_COMMIT();
#pragma unroll
    for (int m = 0; m < 4; m++) {
        int row = wo * 64 + m * 16 + (lane >> 2);
        float b0 = bk[row], b1 = bk[row + 8];
        size_t o0 = ((size_t)(b * C_ + row)) * HW_ + p0;
        size_t o1 = ((size_t)(b * C_ + row + 8)) * HW_ + p0;
        float s0 = 0.f, s1 = 0.f;
#pragma unroll
        for (int n = 0; n < 4; n++) {
            int col = wp * 32 + n * 8 + (c2 << 1);
            half2 h0 = __floats2half2_rn(elu1(acc[m][n][0] + b0), elu1(acc[m][n][1] + b0));
            half2 h1 = __floats2half2_rn(elu1(acc[m][n][2] + b1), elu1(acc[m][n][3] + b1));
            *(half2*)(g_k + o0 + col) = h0;
            *(half2*)(g_k + o1 + col) = h1;
            s0 += __low2float(h0) + __high2float(h0);
            s1 += __low2float(h1) + __high2float(h1);
        }
        s0 += __shfl_xor_sync(~0u, s0, 1); s0 += __shfl_xor_sync(~0u, s0, 2);
        s1 += __shfl_xor_sync(~0u, s1, 1); s1 += __shfl_xor_sync(~0u, s1, 2);
        if (c2 == 0) {
            atomicAdd(&g_ksum[b * C_ + row], s0);
            atomicAdd(&g_ksum[b * C_ + row + 8], s1);
        }
    }
    // ---- V ----
    gemm_body(g_Wh + 131072, xs, Wbuf, tid, lane, wo, wp, acc);
#pragma unroll
    for (int m = 0; m < 4; m++) {
        int row = wo * 64 + m * 16 + (lane >> 2);
        float b0 = bv[row], b1 = bv[row + 8];
        size_t o0 = ((size_t)(b * C_ + row)) * HW_ + p0;
        size_t o1 = ((size_t)(b * C_ + row + 8)) * HW_ + p0;
#pragma unroll
        for (int n = 0; n < 4; n++) {
            int col = wp * 32 + n * 8 + (c2 << 1);
            *(half2*)(g_v + o0 + col) = __floats2half2_rn(acc[m][n][0] + b0, acc[m][n][1] + b0);
            *(half2*)(g_v + o1 + col) = __floats2half2_rn(acc[m][n][2] + b1, acc[m][n][3] + b1);
        }
    }
}

// ---------------- k_kv: 128x128 tiles, split-K, RED into g_kvn ----------------
// block = (s, mh, nh): K rows [mh*128,+128), V rows [nh*128,+128), px slice s*1024.
__device__ __forceinline__ void kv_stage(__half* Kt, int b, int mh, int nh, int p0, int tid) {
#pragma unroll
    for (int i = 0; i < 4; i++) {
        int lin = i * 256 + tid, row = lin >> 3, seg = lin & 7;
        cp16(Kt + row * LDW2 + seg * 8,
             g_k + ((size_t)(b * C_ + mh * 128 + row)) * HW_ + p0 + seg * 8);
    }
#pragma unroll
    for (int i = 0; i < 4; i++) {
        int lin = i * 256 + tid, row = lin >> 3, seg = lin & 7;
        cp16(Kt + 128 * LDW2 + row * LDW2 + seg * 8,
             g_v + ((size_t)(b * C_ + nh * 128 + row)) * HW_ + p0 + seg * 8);
    }
    CP_COMMIT();
}

__global__ void __launch_bounds__(256, 2) k_kv() {
    extern __shared__ __half smh[];
    const int TSZ = 256 * LDW2;   // K 128 rows + V 128 rows
    int s = blockIdx.x >> 2, mh = (blockIdx.x >> 1) & 1, nh = blockIdx.x & 1, b = blockIdx.y;
    int tid = threadIdx.x, lane = tid & 31, warp = tid >> 5;
    int wo = warp & 1, wp = warp >> 1, c2 = lane & 3;   // 2 x 4 warp grid (128 x 128 tile)
    int rowA = lane & 15, colA = (lane & 16) >> 1;
    int rowB = (lane & 7) + ((lane & 16) >> 1), colB = lane & 8;
    float acc[4][4][4];
#pragma unroll
    for (int m = 0; m < 4; m++)
#pragma unroll
        for (int n = 0; n < 4; n++)
#pragma unroll
            for (int i = 0; i < 4; i++) acc[m][n][i] = 0.f;
    kv_stage(smh, b, mh, nh, s * 1024, tid);
#pragma unroll 1
    for (int ch = 0; ch < 16; ch++) {
        CP_WAIT0();
        __syncthreads();
        if (ch < 15) kv_stage(smh + ((ch + 1) & 1) * TSZ, b, mh, nh, s * 1024 + (ch + 1) * 64, tid);
        uint32_t kt = s2u(smh + (ch & 1) * TSZ);
        uint32_t vt = kt + 128 * LDW2 * 2;
#pragma unroll
        for (int ks = 0; ks < 4; ks++) {
            uint32_t A[4][4];
#pragma unroll
            for (int m = 0; m < 4; m++)
                ldsm4(A[m], kt + ((wo * 64 + m * 16 + rowA) * LDW2 + ks * 16 + colA) * 2);
            uint32_t Bv[2][4];
#pragma unroll
            for (int t = 0; t < 2; t++)
                ldsm4(Bv[t], vt + ((wp * 32 + t * 16 + rowB) * LDW2 + ks * 16 + colB) * 2);
#pragma unroll
            for (int m = 0; m < 4; m++)
#pragma unroll
                for (int n = 0; n < 4; n++)
                    mma16(acc[m][n], A[m], Bv[n >> 1][(n & 1) * 2], Bv[n >> 1][(n & 1) * 2 + 1]);
        }
    }
    float* outp = g_kvn + (size_t)b * 65536;
#pragma unroll
    for (int m = 0; m < 4; m++) {
        int row = mh * 128 + wo * 64 + m * 16 + (lane >> 2);
#pragma unroll
        for (int n = 0; n < 4; n++) {
            int col = nh * 128 + wp * 32 + n * 8 + (c2 << 1);
            red2(outp + row * 256 + col, acc[m][n][0], acc[m][n][1]);
            red2(outp + (row + 8) * 256 + col, acc[m][n][2], acc[m][n][3]);
        }
    }
}

__global__ void __launch_bounds__(256) k_red() {
    int gid = blockIdx.x * 256 + threadIdx.x;
    float4 v = *(float4*)(g_kvn + (size_t)gid * 4);
    int row = gid >> 6;
    float inv = 1.0f / (g_ksum[row] + 1e-6f);
    v.x *= inv; v.y *= inv; v.z *= inv; v.w *= inv;
    *(float4*)(g_kvn + (size_t)gid * 4) = v;
}

// ---------------- k_m: M = Wp @ kvn ----------------
__global__ void __launch_bounds__(256, 2) k_m() {
    extern __shared__ __half smh[];
    __half* Xs = smh;
    __half* Wbuf = smh + 256 * LDXS;
    int b = blockIdx.y, d0 = blockIdx.x * 64;
    int tid = threadIdx.x, lane = tid & 31, warp = tid >> 5;
    int wo = warp & 3, wp_ = warp >> 2, c2 = lane & 3;
    uint32_t xs = s2u(Xs);
    stageW64(Wbuf, g_Wh + 196608, tid); CP_COMMIT();
#pragma unroll
    for (int i = 0; i < 16; i++) {
        int lin = i * 256 + tid, c = lin >> 4, d4 = (lin & 15) << 2;
        float4 v = *(const float4*)(g_kvn + (size_t)(b * C_ + c) * C_ + d0 + d4);
        *(half2*)(Xs + c * LDXS + d4) = __floats2half2_rn(v.x, v.y);
        *(half2*)(Xs + c * LDXS + d4 + 2) = __floats2half2_rn(v.z, v.w);
    }
    float acc[4][4][4];
    gemm_body(g_Wh + 196608, xs, Wbuf, tid, lane, wo, wp_, acc);
    __half* dst = g_M + (size_t)b * 65536;
#pragma unroll
    for (int m = 0; m < 4; m++) {
        int row = wo * 64 + m * 16 + (lane >> 2);
#pragma unroll
        for (int n = 0; n < 4; n++) {
            int col = d0 + wp_ * 32 + n * 8 + (c2 << 1);
            *(half2*)(dst + row * 256 + col) = __floats2half2_rn(acc[m][n][0], acc[m][n][1]);
            *(half2*)(dst + (row + 8) * 256 + col) = __floats2half2_rn(acc[m][n][2], acc[m][n][3]);
        }
    }
}

// ---------------- k_out: out = M @ q + bp + x (cp.async Xs fill) ----------------
__global__ void __launch_bounds__(256, 2) k_out(const float* __restrict__ x,
                                                const float* __restrict__ bp, float* __restrict__ out) {
    extern __shared__ __half smh[];
    __half* Xs = smh;
    __half* Wbuf = smh + 256 * LDXS;
    int b = blockIdx.y, p0 = blockIdx.x * 64;
    int tid = threadIdx.x, lane = tid & 31, warp = tid >> 5;
    int wo = warp & 3, wp = warp >> 2, c2 = lane & 3;
    uint32_t xs = s2u(Xs);
    const __half* Asrc = g_M + (size_t)b * 65536;
    stageW64(Wbuf, Asrc, tid); CP_COMMIT();
    // Xs fill via cp.async (pure half copy, overlaps with M chunk0 stage)
#pragma unroll
    for (int i = 0; i < 8; i++) {
        int lin = i * 256 + tid, d = lin >> 3, seg = lin & 7;
        cp16(Xs + d * LDXS + seg * 8, g_q + ((size_t)(b * C_ + d)) * HW_ + p0 + seg * 8);
    }
    CP_COMMIT();
    float acc[4][4][4];
    gemm_body(Asrc, xs, Wbuf, tid, lane, wo, wp, acc);
#pragma unroll
    for (int m = 0; m < 4; m++) {
        int row = wo * 64 + m * 16 + (lane >> 2);
        float b0 = bp[row], b1 = bp[row + 8];
        size_t o0 = ((size_t)(b * C_ + row)) * HW_ + p0;
        size_t o1 = ((size_t)(b * C_ + row + 8)) * HW_ + p0;
#pragma unroll
        for (int n = 0; n < 4; n++) {
            int col = wp * 32 + n * 8 + (c2 << 1);
            float2 x0 = *(const float2*)(x + o0 + col);
            float2 x1 = *(const float2*)(x + o1 + col);
            *(float2*)(out + o0 + col) = make_float2(acc[m][n][0] + b0 + x0.x, acc[m][n][1] + b0 + x0.y);
            *(float2*)(out + o1 + col) = make_float2(acc[m][n][2] + b1 + x1.x, acc[m][n][3] + b1 + x1.y);
        }
    }
}

extern "C" void kernel_launch(void* const* d_in, const int* in_sizes, int n_in,
                              void* d_out, int out_size) {
    const float* x = (const float*)d_in[0];
    const float* gamma = (const float*)d_in[1];
    const float* beta = (const float*)d_in[2];
    const float* Wq = (const float*)d_in[3];
    const float* bq = (const float*)d_in[4];
    const float* Wk = (const float*)d_in[5];
    const float* bk = (const float*)d_in[6];
    const float* Wv = (const float*)d_in[7];
    const float* bv = (const float*)d_in[8];
    const float* Wp = (const float*)d_in[9];
    const float* bp = (const float*)d_in[10];
    float* out = (float*)d_out;

    const int SMEM_QKV = (256 * LDXS + 2 * SZW2) * 2 + 2048;  // 112640 B
    const int SMEM_GEMM = (256 * LDXS + 2 * SZW2) * 2;        // 110592 B
    const int SMEM_KV = 2 * 256 * LDW2 * 2;                    // 73728 B
    cudaFuncSetAttribute(k_qkv, cudaFuncAttributeMaxDynamicSharedMemorySize, SMEM_QKV);
    cudaFuncSetAttribute(k_m, cudaFuncAttributeMaxDynamicSharedMemorySize, SMEM_GEMM);
    cudaFuncSetAttribute(k_out, cudaFuncAttributeMaxDynamicSharedMemorySize, SMEM_GEMM);
    cudaFuncSetAttribute(k_kv, cudaFuncAttributeMaxDynamicSharedMemorySize, SMEM_KV);

    k0_zero<<<512, 256>>>();
    k_prep<<<256, 256>>>(Wq, Wk, Wv, Wp);
    k_stats<<<dim3(16, 64), 256>>>(x);
    k_qkv<<<dim3(256, 8), 256, SMEM_QKV>>>(x, gamma, beta, bq, bk, bv);
    k_kv<<<dim3(64, 8), 256, SMEM_KV>>>();
    k_red<<<512, 256>>>();
    k_m<<<dim3(4, 8), 256, SMEM_GEMM>>>();
    k_out<<<dim3(256, 8), 256, SMEM_GEMM>>>(x, bp, out);
}